// round 2
// baseline (speedup 1.0000x reference)
#include <cuda_runtime.h>

// RecurrentDNNC: y_t = relu(M x_t + B y_{t-1} + c); out_t = sigmoid(W2 y_t + b2)
// Chunked-parallel scan with warm-up window (state forgets geometrically under
// the contractive relu-affine map). Each thread owns CHUNK output steps and
// runs WARM extra steps before its chunk starting from y=0.

#define SEQ_LEN (1 << 21)
#define CHUNK   128
#define WARM    256
#define NTH     (SEQ_LEN / CHUNK)   // 16384 threads
#define BLOCK   64
#define GRID    (NTH / BLOCK)       // 256 blocks

__device__ __forceinline__ float ex2_approx(float x) {
    float r; asm("ex2.approx.f32 %0, %1;" : "=f"(r) : "f"(x)); return r;
}
__device__ __forceinline__ float rcp_approx(float x) {
    float r; asm("rcp.approx.f32 %0, %1;" : "=f"(r) : "f"(x)); return r;
}

__global__ void __launch_bounds__(BLOCK, 1)
rdnnc_kernel(const float4* __restrict__ x,
             const float*  __restrict__ W1, const float* __restrict__ b1,
             const float*  __restrict__ Wd, const float* __restrict__ bd,
             const float*  __restrict__ W2, const float* __restrict__ b2,
             float2*       __restrict__ out)
{
    const int t = blockIdx.x * BLOCK + threadIdx.x;

    // ---- derived parameters (tiny, L1/L2-resident loads) ----
    // Wd rows: [A | B], A multiplies h_t, B multiplies y_{t-1}
    const float A00 = Wd[0], A01 = Wd[1], B00 = Wd[2], B01 = Wd[3];
    const float A10 = Wd[4], A11 = Wd[5], B10 = Wd[6], B11 = Wd[7];

    // M = A @ W1  (2x4): fold fc1 into the cell.  W1 is (H=2, IN=4) row-major.
    const float M00 = A00 * W1[0] + A01 * W1[4];
    const float M01 = A00 * W1[1] + A01 * W1[5];
    const float M02 = A00 * W1[2] + A01 * W1[6];
    const float M03 = A00 * W1[3] + A01 * W1[7];
    const float M10 = A10 * W1[0] + A11 * W1[4];
    const float M11 = A10 * W1[1] + A11 * W1[5];
    const float M12 = A10 * W1[2] + A11 * W1[6];
    const float M13 = A10 * W1[3] + A11 * W1[7];

    // c = A @ b1 + bd
    const float c0 = A00 * b1[0] + A01 * b1[1] + bd[0];
    const float c1 = A10 * b1[0] + A11 * b1[1] + bd[1];

    // Output head pre-scaled by -log2(e): sigmoid(z) = 1 / (1 + 2^(-z*log2e))
    const float L2E = 1.4426950408889634f;
    const float w00 = -L2E * W2[0], w01 = -L2E * W2[1];
    const float w10 = -L2E * W2[2], w11 = -L2E * W2[3];
    const float v0  = -L2E * b2[0], v1  = -L2E * b2[1];

    const int start  = t * CHUNK;
    int       wstart = start - WARM;
    if (wstart < 0) wstart = 0;

    float y0 = 0.f, y1 = 0.f;

    // ---- warm-up: recurrence only ----
    #pragma unroll 4
    for (int i = wstart; i < start; ++i) {
        const float4 q = x[i];
        const float s0 = fmaf(M00, q.x, fmaf(M01, q.y, fmaf(M02, q.z, fmaf(M03, q.w, c0))));
        const float s1 = fmaf(M10, q.x, fmaf(M11, q.y, fmaf(M12, q.z, fmaf(M13, q.w, c1))));
        const float n0 = fmaxf(fmaf(B00, y0, fmaf(B01, y1, s0)), 0.f);
        const float n1 = fmaxf(fmaf(B10, y0, fmaf(B11, y1, s1)), 0.f);
        y0 = n0; y1 = n1;
    }

    // ---- main chunk: recurrence + sigmoid head + store ----
    #pragma unroll 8
    for (int i = start; i < start + CHUNK; ++i) {
        const float4 q = x[i];
        const float s0 = fmaf(M00, q.x, fmaf(M01, q.y, fmaf(M02, q.z, fmaf(M03, q.w, c0))));
        const float s1 = fmaf(M10, q.x, fmaf(M11, q.y, fmaf(M12, q.z, fmaf(M13, q.w, c1))));
        const float n0 = fmaxf(fmaf(B00, y0, fmaf(B01, y1, s0)), 0.f);
        const float n1 = fmaxf(fmaf(B10, y0, fmaf(B11, y1, s1)), 0.f);
        y0 = n0; y1 = n1;

        const float z0 = fmaf(w00, y0, fmaf(w01, y1, v0));  // -log2e*(W2 y + b2)[0]
        const float z1 = fmaf(w10, y0, fmaf(w11, y1, v1));
        const float r0 = rcp_approx(1.f + ex2_approx(z0));
        const float r1 = rcp_approx(1.f + ex2_approx(z1));
        out[i] = make_float2(r0, r1);
    }
}

extern "C" void kernel_launch(void* const* d_in, const int* in_sizes, int n_in,
                              void* d_out, int out_size)
{
    // inputs (metadata order): x, W1, b1, Wd, bd, W2, b2, length
    rdnnc_kernel<<<GRID, BLOCK>>>(
        (const float4*)d_in[0],
        (const float*)d_in[1], (const float*)d_in[2],
        (const float*)d_in[3], (const float*)d_in[4],
        (const float*)d_in[5], (const float*)d_in[6],
        (float2*)d_out);
}

// round 5
// speedup vs baseline: 1.1795x; 1.1795x over previous
#include <cuda_runtime.h>
#include <cstdint>

// RecurrentDNNC: y_t = relu(M x_t + B y_{t-1} + c); out_t = sigmoid(W2 y_t + b2)
// Chunked-parallel approximate scan with warm-up window, SMEM-transposed
// coalesced I/O and a 3-stage cp.async pipeline.

#define SEQ     (1 << 21)
#define CHUNK   64
#define WARM    128
#define BLOCK   64
#define GRID    (SEQ / CHUNK / BLOCK)   // 512 blocks, 32768 threads
#define T       8                        // steps per tile
#define STEPS   (WARM + CHUNK)           // 192
#define NT      (STEPS / T)              // 24 tiles
#define WTILES  (WARM / T)               // 16 warm tiles

__device__ __forceinline__ float ex2_approx(float x) {
    float r; asm("ex2.approx.f32 %0, %1;" : "=f"(r) : "f"(x)); return r;
}
__device__ __forceinline__ float rcp_approx(float x) {
    float r; asm("rcp.approx.f32 %0, %1;" : "=f"(r) : "f"(x)); return r;
}
__device__ __forceinline__ void cp_async16(uint32_t dst, const void* src) {
    asm volatile("cp.async.cg.shared.global [%0], [%1], 16;" :: "r"(dst), "l"(src));
}
__device__ __forceinline__ void cp_commit() { asm volatile("cp.async.commit_group;"); }
__device__ __forceinline__ void cp_wait1()  { asm volatile("cp.async.wait_group 1;"); }

// out-staging swizzle: float4 slot for (strip u, step-pair jp); conflict-free for
// both the write phase (fixed jp, u = lane) and the coalesced read phase.
__device__ __forceinline__ int so_idx(int u, int jp) {
    return 4 * u + (((u >> 1) ^ jp) & 3);
}

__global__ void __launch_bounds__(BLOCK, 4)
rdnnc_kernel(const float4* __restrict__ x,
             const float*  __restrict__ W1, const float* __restrict__ b1,
             const float*  __restrict__ Wd, const float* __restrict__ bd,
             const float*  __restrict__ W2, const float* __restrict__ b2,
             float4*       __restrict__ out4)
{
    __shared__ float4 sx[3][T][BLOCK + 1];   // x tiles, padded rows (conflict-free)
    __shared__ float4 so[2][BLOCK * 4];      // out staging, swizzled

    const int tid   = threadIdx.x;
    const int gbase = (int)blockIdx.x * (BLOCK * CHUNK) - WARM;
    const int w0    = gbase + tid * CHUNK;   // this thread's warm-start step

    // ---- fold parameters ----
    const float A00 = Wd[0], A01 = Wd[1], B00 = Wd[2], B01 = Wd[3];
    const float A10 = Wd[4], A11 = Wd[5], B10 = Wd[6], B11 = Wd[7];

    const float M00 = A00*W1[0] + A01*W1[4];
    const float M01 = A00*W1[1] + A01*W1[5];
    const float M02 = A00*W1[2] + A01*W1[6];
    const float M03 = A00*W1[3] + A01*W1[7];
    const float M10 = A10*W1[0] + A11*W1[4];
    const float M11 = A10*W1[1] + A11*W1[5];
    const float M12 = A10*W1[2] + A11*W1[6];
    const float M13 = A10*W1[3] + A11*W1[7];

    const float c0 = A00*b1[0] + A01*b1[1] + bd[0];
    const float c1 = A10*b1[0] + A11*b1[1] + bd[1];

    const float L2E = 1.4426950408889634f;
    const float w00 = -L2E*W2[0], w01 = -L2E*W2[1];
    const float w10 = -L2E*W2[2], w11 = -L2E*W2[3];
    const float v0  = -L2E*b2[0], v1  = -L2E*b2[1];

    const uint32_t sx_base = (uint32_t)__cvta_generic_to_shared(&sx[0][0][0]);

    // recurrent state — declared BEFORE the lambdas that capture it
    float y0_ = 0.f, y1_ = 0.f;

    // coalesced tile load: tile = strips u 0..63 x steps [i0, i0+8)
    auto load_tile = [&](int buf, int i0) {
        const uint32_t bbase = sx_base + (uint32_t)buf * (T * (BLOCK + 1) * 16);
        #pragma unroll
        for (int l = 0; l < T; ++l) {
            const int e = l * BLOCK + tid;       // global-memory order -> coalesced
            const int u = e >> 3;
            const int j = e & 7;
            int g = gbase + u * CHUNK + i0 + j;
            if (g < 0) g = 0;                    // clamp addr; value unused (tile skipped)
            cp_async16(bbase + (uint32_t)((j * (BLOCK + 1) + u) << 4), x + g);
        }
    };

    // one recurrence step
    auto step = [&](const float4 q) {
        const float s0 = fmaf(M00,q.x, fmaf(M01,q.y, fmaf(M02,q.z, fmaf(M03,q.w, c0))));
        const float s1 = fmaf(M10,q.x, fmaf(M11,q.y, fmaf(M12,q.z, fmaf(M13,q.w, c1))));
        const float n0 = fmaxf(fmaf(B00,y0_, fmaf(B01,y1_, s0)), 0.f);
        const float n1 = fmaxf(fmaf(B10,y0_, fmaf(B11,y1_, s1)), 0.f);
        y0_ = n0; y1_ = n1;
    };

    load_tile(0, 0);  cp_commit();
    load_tile(1, T);  cp_commit();

    int pend = -1;

    for (int t = 0; t < NT; ++t) {
        const int cur = t % 3;
        cp_wait1();
        __syncthreads();

        if (t + 2 < NT) load_tile((t + 2) % 3, (t + 2) * T);
        cp_commit();                         // empty group OK; keeps wait invariant

        if (pend >= 0) {                     // drain staged output, coalesced
            const int base4 = (gbase + pend * T) >> 1;
            #pragma unroll
            for (int l = 0; l < 4; ++l) {
                const int e  = l * BLOCK + tid;
                const int u  = e >> 2;
                const int jp = e & 3;
                out4[base4 + u * 32 + jp] = so[pend & 1][so_idx(u, jp)];
            }
        }

        if (t < WTILES) {
            // warm tile; tile-aligned skip = exact y=0 clamp for w0 < 0 threads
            if (w0 + t * T >= 0) {
                #pragma unroll
                for (int j = 0; j < T; ++j) step(sx[cur][j][tid]);
            }
        } else {
            #pragma unroll
            for (int jp = 0; jp < 4; ++jp) {
                step(sx[cur][2*jp][tid]);
                const float z0 = fmaf(w00,y0_, fmaf(w01,y1_, v0));
                const float z1 = fmaf(w10,y0_, fmaf(w11,y1_, v1));
                const float r0 = rcp_approx(1.f + ex2_approx(z0));
                const float r1 = rcp_approx(1.f + ex2_approx(z1));

                step(sx[cur][2*jp+1][tid]);
                const float z2 = fmaf(w00,y0_, fmaf(w01,y1_, v0));
                const float z3 = fmaf(w10,y0_, fmaf(w11,y1_, v1));
                const float r2 = rcp_approx(1.f + ex2_approx(z2));
                const float r3 = rcp_approx(1.f + ex2_approx(z3));

                so[t & 1][so_idx(tid, jp)] = make_float4(r0, r1, r2, r3);
            }
            pend = t;
        }
    }

    __syncthreads();
    {   // flush last main tile
        const int base4 = (gbase + (NT - 1) * T) >> 1;
        #pragma unroll
        for (int l = 0; l < 4; ++l) {
            const int e  = l * BLOCK + tid;
            const int u  = e >> 2;
            const int jp = e & 3;
            out4[base4 + u * 32 + jp] = so[(NT - 1) & 1][so_idx(u, jp)];
        }
    }
}

extern "C" void kernel_launch(void* const* d_in, const int* in_sizes, int n_in,
                              void* d_out, int out_size)
{
    rdnnc_kernel<<<GRID, BLOCK>>>(
        (const float4*)d_in[0],
        (const float*)d_in[1], (const float*)d_in[2],
        (const float*)d_in[3], (const float*)d_in[4],
        (const float*)d_in[5], (const float*)d_in[6],
        (float4*)d_out);
}

// round 7
// speedup vs baseline: 2.5660x; 2.1755x over previous
#include <cuda_runtime.h>
#include <cstdint>

// RecurrentDNNC: y_t = relu(M x_t + B y_{t-1} + c); out_t = sigmoid(W2 y_t + b2)
// Block-resident scheme: WARM == CHUNK == 64, so thread u's warm window is
// exactly strip (u-1)'s main chunk. The block bulk-loads its whole x range
// (65 strips x 64 steps, incl. one strip of the previous block) into SMEM once
// via 8 per-tile cp.async groups; warm reads strip tid, main reads strip tid+1.

#define SEQ    (1 << 21)
#define BLOCK  64
#define CHUNK  64
#define WARM   64
#define GRID   (SEQ / (BLOCK * CHUNK))   // 512 blocks
#define T      8                          // steps per tile
#define NTILE  8                          // tiles covering the 64-step chunk
#define NSTRIP 65                         // strips -1..63  (s = chunkIdx + 1)

__device__ __forceinline__ float ex2_approx(float x) {
    float r; asm("ex2.approx.f32 %0, %1;" : "=f"(r) : "f"(x)); return r;
}
__device__ __forceinline__ float rcp_approx(float x) {
    float r; asm("rcp.approx.f32 %0, %1;" : "=f"(r) : "f"(x)); return r;
}
__device__ __forceinline__ void cp_async16(uint32_t dst, const void* src) {
    asm volatile("cp.async.cg.shared.global [%0], [%1], 16;" :: "r"(dst), "l"(src));
}
__device__ __forceinline__ void cp_commit() { asm volatile("cp.async.commit_group;"); }

// out-staging swizzle (bank-conflict-free for both write and drain phases)
__device__ __forceinline__ int so_idx(int u, int jp) {
    return 4 * u + (((u >> 1) ^ jp) & 3);
}

__global__ void __launch_bounds__(BLOCK, 3)
rdnnc_kernel(const float4* __restrict__ x,
             const float*  __restrict__ W1, const float* __restrict__ b1,
             const float*  __restrict__ Wd, const float* __restrict__ bd,
             const float*  __restrict__ W2, const float* __restrict__ b2,
             float4*       __restrict__ out4)
{
    // x window: [tile][strip][step ^ (strip&7)]  -> conflict-free LDS.128 per
    // 8-lane phase (chunk index s*8 + j^(s&7) distinct mod 8 within a phase)
    __shared__ float4 sx[NTILE][NSTRIP][T];     // 65 KB
    __shared__ float4 so[2][BLOCK * 4];         // 8 KB out staging

    const int tid        = threadIdx.x;
    const int blockStart = (int)blockIdx.x * (BLOCK * CHUNK);

    // ---- fold parameters (tiny L1/L2-resident loads) ----
    const float A00 = Wd[0], A01 = Wd[1], B00 = Wd[2], B01 = Wd[3];
    const float A10 = Wd[4], A11 = Wd[5], B10 = Wd[6], B11 = Wd[7];

    const float M00 = A00*W1[0] + A01*W1[4];
    const float M01 = A00*W1[1] + A01*W1[5];
    const float M02 = A00*W1[2] + A01*W1[6];
    const float M03 = A00*W1[3] + A01*W1[7];
    const float M10 = A10*W1[0] + A11*W1[4];
    const float M11 = A10*W1[1] + A11*W1[5];
    const float M12 = A10*W1[2] + A11*W1[6];
    const float M13 = A10*W1[3] + A11*W1[7];

    const float c0 = A00*b1[0] + A01*b1[1] + bd[0];
    const float c1 = A10*b1[0] + A11*b1[1] + bd[1];

    const float L2E = 1.4426950408889634f;
    const float w00 = -L2E*W2[0], w01 = -L2E*W2[1];
    const float w10 = -L2E*W2[2], w11 = -L2E*W2[3];
    const float v0  = -L2E*b2[0], v1  = -L2E*b2[1];

    float y0_ = 0.f, y1_ = 0.f;
    auto step = [&](const float4 q) {
        const float s0 = fmaf(M00,q.x, fmaf(M01,q.y, fmaf(M02,q.z, fmaf(M03,q.w, c0))));
        const float s1 = fmaf(M10,q.x, fmaf(M11,q.y, fmaf(M12,q.z, fmaf(M13,q.w, c1))));
        const float n0 = fmaxf(fmaf(B00,y0_, fmaf(B01,y1_, s0)), 0.f);
        const float n1 = fmaxf(fmaf(B10,y0_, fmaf(B11,y1_, s1)), 0.f);
        y0_ = n0; y1_ = n1;
    };

    // thread 0 of block 0 has no warm data (starts exactly at y=0) — exact skip
    const bool do_warm = (blockStart + tid * CHUNK - WARM) >= 0;

    const uint32_t sx_base = (uint32_t)__cvta_generic_to_shared(&sx[0][0][0]);

    // ---- issue all 8 tile loads (coalesced: 8 consecutive float4 per strip run)
    #pragma unroll
    for (int tau = 0; tau < NTILE; ++tau) {
        const int gt = blockStart - WARM + tau * T;   // strip s covers gt + s*64 + j
        #pragma unroll
        for (int e = tid; e < NSTRIP * T; e += BLOCK) {
            const int s = e >> 3;
            const int j = e & 7;
            int g = gt + s * CHUNK + j;
            if (g < 0) g = 0;                          // block 0, strip -1: value unused
            cp_async16(sx_base + (uint32_t)((((tau * NSTRIP + s) * T) + (j ^ (s & 7))) << 4),
                       x + g);
        }
        cp_commit();
    }

    // ---- warm phase: tile tau usable once groups pending <= 7-tau ----
    const int jx_w = tid & 7;
#define WARM_TILE(TAU, NW)                                                  \
    asm volatile("cp.async.wait_group " #NW ";" ::: "memory");              \
    __syncthreads();                                                        \
    if (do_warm) {                                                          \
        _Pragma("unroll")                                                   \
        for (int j = 0; j < T; ++j) step(sx[TAU][tid][j ^ jx_w]);           \
    }
    WARM_TILE(0, 7)
    WARM_TILE(1, 6)
    WARM_TILE(2, 5)
    WARM_TILE(3, 4)
    WARM_TILE(4, 3)
    WARM_TILE(5, 2)
    WARM_TILE(6, 1)
    WARM_TILE(7, 0)
#undef WARM_TILE

    // ---- main phase: same tiles, strip tid+1; stage outputs, drain coalesced
    const int s_main = tid + 1;
    const int jx_m   = s_main & 7;

    for (int tau = 0; tau < NTILE; ++tau) {
        #pragma unroll
        for (int jp = 0; jp < 4; ++jp) {
            step(sx[tau][s_main][(2*jp) ^ jx_m]);
            const float z0 = fmaf(w00,y0_, fmaf(w01,y1_, v0));
            const float z1 = fmaf(w10,y0_, fmaf(w11,y1_, v1));
            const float r0 = rcp_approx(1.f + ex2_approx(z0));
            const float r1 = rcp_approx(1.f + ex2_approx(z1));

            step(sx[tau][s_main][(2*jp + 1) ^ jx_m]);
            const float z2 = fmaf(w00,y0_, fmaf(w01,y1_, v0));
            const float z3 = fmaf(w10,y0_, fmaf(w11,y1_, v1));
            const float r2 = rcp_approx(1.f + ex2_approx(z2));
            const float r3 = rcp_approx(1.f + ex2_approx(z3));

            so[tau & 1][so_idx(tid, jp)] = make_float4(r0, r1, r2, r3);
        }
        __syncthreads();   // staged writes visible; also fences prior drain reuse

        const int base4 = (blockStart >> 1) + tau * 4;   // float4 index
        #pragma unroll
        for (int l = 0; l < 4; ++l) {
            const int e  = l * BLOCK + tid;
            const int u  = e >> 2;
            const int jp = e & 3;
            out4[base4 + u * 32 + jp] = so[tau & 1][so_idx(u, jp)];
        }
    }
}

extern "C" void kernel_launch(void* const* d_in, const int* in_sizes, int n_in,
                              void* d_out, int out_size)
{
    rdnnc_kernel<<<GRID, BLOCK>>>(
        (const float4*)d_in[0],
        (const float*)d_in[1], (const float*)d_in[2],
        (const float*)d_in[3], (const float*)d_in[4],
        (const float*)d_in[5], (const float*)d_in[6],
        (float4*)d_out);
}

// round 8
// speedup vs baseline: 2.8814x; 1.1229x over previous
#include <cuda_runtime.h>
#include <cstdint>

// RecurrentDNNC: y_t = relu(M x_t + B y_{t-1} + c); out_t = sigmoid(W2 y_t + b2)
// Fold-at-load scheme: coalesced LDG of x, fold s_t = M x_t + c ONCE per element
// into transposed SMEM (float2), then warm (neighbor strip) + main recurrence
// read LDS.64. 1-warp blocks, 1024 blocks, ~9 resident/SM.

#define SEQ     (1 << 21)
#define BLOCK   32
#define CHUNK   64
#define WARM    64                       // == CHUNK: warm window = neighbor strip
#define GRID    (SEQ / (BLOCK * CHUNK))  // 1024 blocks
#define NSTRIP  (BLOCK + 1)              // strips -1..31
#define NELEM   (NSTRIP * CHUNK)         // 2112 float4 per block
#define NITER   (NELEM / BLOCK)          // 66 loads per thread

__device__ __forceinline__ float ex2_approx(float x) {
    float r; asm("ex2.approx.f32 %0, %1;" : "=f"(r) : "f"(x)); return r;
}
__device__ __forceinline__ float rcp_approx(float x) {
    float r; asm("rcp.approx.f32 %0, %1;" : "=f"(r) : "f"(x)); return r;
}

__global__ void __launch_bounds__(BLOCK, 8)
rdnnc_kernel(const float4* __restrict__ x,
             const float*  __restrict__ W1, const float* __restrict__ b1,
             const float*  __restrict__ Wd, const float* __restrict__ bd,
             const float*  __restrict__ W2, const float* __restrict__ b2,
             float4*       __restrict__ out4)
{
    // folded inputs, transposed: [strip][step], +1 float2 pad per row =>
    // strip stride 65*8B -> bank shift 2/strip, conflict-free per half-warp
    __shared__ float2 ss[NSTRIP][CHUNK + 1];   // ~17 KB
    __shared__ float4 so[2][BLOCK * 8];        // 8 KB out staging (16-step segs)

    const int tid       = threadIdx.x;
    const int blockBase = (int)blockIdx.x * (BLOCK * CHUNK) - CHUNK; // step of e=0

    // ---- fold parameters (tiny L1/L2-resident loads) ----
    const float A00 = Wd[0], A01 = Wd[1], B00 = Wd[2], B01 = Wd[3];
    const float A10 = Wd[4], A11 = Wd[5], B10 = Wd[6], B11 = Wd[7];

    const float M00 = A00*W1[0] + A01*W1[4];
    const float M01 = A00*W1[1] + A01*W1[5];
    const float M02 = A00*W1[2] + A01*W1[6];
    const float M03 = A00*W1[3] + A01*W1[7];
    const float M10 = A10*W1[0] + A11*W1[4];
    const float M11 = A10*W1[1] + A11*W1[5];
    const float M12 = A10*W1[2] + A11*W1[6];
    const float M13 = A10*W1[3] + A11*W1[7];

    const float c0 = A00*b1[0] + A01*b1[1] + bd[0];
    const float c1 = A10*b1[0] + A11*b1[1] + bd[1];

    const float L2E = 1.4426950408889634f;
    const float w00 = -L2E*W2[0], w01 = -L2E*W2[1];
    const float w10 = -L2E*W2[2], w11 = -L2E*W2[3];
    const float v0  = -L2E*b2[0], v1  = -L2E*b2[1];

    // ---- fold phase: coalesced LDG.128 -> 8 FFMA -> STS.64 (once per element)
    #pragma unroll 6
    for (int i = 0; i < NITER; ++i) {
        const int e = i * BLOCK + tid;           // linear, coalesced
        int g = blockBase + e;
        if (g < 0) g = 0;                        // block 0, strip -1: value unused
        const float4 q = x[g];
        const float s0 = fmaf(M00,q.x, fmaf(M01,q.y, fmaf(M02,q.z, fmaf(M03,q.w, c0))));
        const float s1 = fmaf(M10,q.x, fmaf(M11,q.y, fmaf(M12,q.z, fmaf(M13,q.w, c1))));
        ss[e >> 6][e & 63] = make_float2(s0, s1);
    }
    __syncthreads();                              // 1 warp: cheap

    // ---- recurrence ----
    float y0_ = 0.f, y1_ = 0.f;
    auto step = [&](const float2 s) {
        const float n0 = fmaxf(fmaf(B00,y0_, fmaf(B01,y1_, s.x)), 0.f);
        const float n1 = fmaxf(fmaf(B10,y0_, fmaf(B11,y1_, s.y)), 0.f);
        y0_ = n0; y1_ = n1;
    };

    // warm: strip tid (= previous chunk). Block 0 / thread 0 starts exactly at y=0.
    if ((blockIdx.x | tid) != 0) {
        #pragma unroll 8
        for (int j = 0; j < WARM; ++j) step(ss[tid][j]);
    }

    // main: strip tid+1; head + swizzled staging, drain every 16 steps (128B runs)
    const int sm      = tid + 1;
    const int o4base  = (int)blockIdx.x * 1024;   // block covers 1024 float4 of out

    #pragma unroll
    for (int seg = 0; seg < 4; ++seg) {
        #pragma unroll
        for (int p = 0; p < 8; ++p) {             // p = float4 pair within segment
            step(ss[sm][seg*16 + 2*p]);
            const float z0 = fmaf(w00,y0_, fmaf(w01,y1_, v0));
            const float z1 = fmaf(w10,y0_, fmaf(w11,y1_, v1));
            const float r0 = rcp_approx(1.f + ex2_approx(z0));
            const float r1 = rcp_approx(1.f + ex2_approx(z1));

            step(ss[sm][seg*16 + 2*p + 1]);
            const float z2 = fmaf(w00,y0_, fmaf(w01,y1_, v0));
            const float z3 = fmaf(w10,y0_, fmaf(w11,y1_, v1));
            const float r2 = rcp_approx(1.f + ex2_approx(z2));
            const float r3 = rcp_approx(1.f + ex2_approx(z3));

            so[seg & 1][tid * 8 + ((tid ^ p) & 7)] = make_float4(r0, r1, r2, r3);
        }
        __syncwarp();

        #pragma unroll
        for (int l = 0; l < 8; ++l) {             // drain: 128B contiguous per strip
            const int e = l * BLOCK + tid;
            const int u = e >> 3;
            const int p = e & 7;
            out4[o4base + u * 32 + seg * 8 + p] = so[seg & 1][u * 8 + ((u ^ p) & 7)];
        }
        __syncwarp();
    }
}

extern "C" void kernel_launch(void* const* d_in, const int* in_sizes, int n_in,
                              void* d_out, int out_size)
{
    rdnnc_kernel<<<GRID, BLOCK>>>(
        (const float4*)d_in[0],
        (const float*)d_in[1], (const float*)d_in[2],
        (const float*)d_in[3], (const float*)d_in[4],
        (const float*)d_in[5], (const float*)d_in[6],
        (float4*)d_out);
}

// round 10
// speedup vs baseline: 3.3333x; 1.1569x over previous
#include <cuda_runtime.h>
#include <cstdint>

// RecurrentDNNC: y_t = relu(M x_t + B y_{t-1} + c); out_t = sigmoid(W2 y_t + b2)
// Fold-at-load scheme, high-MLP fold: 3 batches of 22 LDG.128 into registers
// (MLP=22), fold s_t = M x_t + c once per element into transposed SMEM, then
// warm (neighbor strip) + main recurrence read LDS.64. 1-warp blocks.

#define SEQ     (1 << 21)
#define BLOCK   32
#define CHUNK   64
#define WARM    64                       // == CHUNK: warm window = neighbor strip
#define GRID    (SEQ / (BLOCK * CHUNK))  // 1024 blocks
#define NSTRIP  (BLOCK + 1)              // strips -1..31
#define NELEM   (NSTRIP * CHUNK)         // 2112 float4 per block
#define NB      22                       // loads per batch (MLP)
#define NBATCH  3                        // 3 * 22 * 32 = 2112

__device__ __forceinline__ float ex2_approx(float x) {
    float r; asm("ex2.approx.f32 %0, %1;" : "=f"(r) : "f"(x)); return r;
}
__device__ __forceinline__ float rcp_approx(float x) {
    float r; asm("rcp.approx.f32 %0, %1;" : "=f"(r) : "f"(x)); return r;
}

__global__ void __launch_bounds__(BLOCK, 8)
rdnnc_kernel(const float4* __restrict__ x,
             const float*  __restrict__ W1, const float* __restrict__ b1,
             const float*  __restrict__ Wd, const float* __restrict__ bd,
             const float*  __restrict__ W2, const float* __restrict__ b2,
             float4*       __restrict__ out4)
{
    // folded inputs, transposed: [strip][step], +1 float2 pad per row
    __shared__ float2 ss[NSTRIP][CHUNK + 1];   // ~17 KB
    __shared__ float4 so[BLOCK * 8];           // 4 KB out staging (16-step segs)

    const int tid       = threadIdx.x;
    const int blockBase = (int)blockIdx.x * (BLOCK * CHUNK) - CHUNK; // step of e=0

    // ---- fold parameters (tiny L1/L2-resident loads) ----
    const float A00 = Wd[0], A01 = Wd[1], B00 = Wd[2], B01 = Wd[3];
    const float A10 = Wd[4], A11 = Wd[5], B10 = Wd[6], B11 = Wd[7];

    const float M00 = A00*W1[0] + A01*W1[4];
    const float M01 = A00*W1[1] + A01*W1[5];
    const float M02 = A00*W1[2] + A01*W1[6];
    const float M03 = A00*W1[3] + A01*W1[7];
    const float M10 = A10*W1[0] + A11*W1[4];
    const float M11 = A10*W1[1] + A11*W1[5];
    const float M12 = A10*W1[2] + A11*W1[6];
    const float M13 = A10*W1[3] + A11*W1[7];

    const float c0 = A00*b1[0] + A01*b1[1] + bd[0];
    const float c1 = A10*b1[0] + A11*b1[1] + bd[1];

    const float L2E = 1.4426950408889634f;
    const float w00 = -L2E*W2[0], w01 = -L2E*W2[1];
    const float w10 = -L2E*W2[2], w11 = -L2E*W2[3];
    const float v0  = -L2E*b2[0], v1  = -L2E*b2[1];

    // ---- fold phase: batched coalesced LDG.128 (MLP=22) -> 8 FFMA -> STS.64
    #pragma unroll
    for (int i = 0; i < NBATCH; ++i) {
        float4 q[NB];
        #pragma unroll
        for (int b = 0; b < NB; ++b) {
            const int e = (i * NB + b) * BLOCK + tid;    // coalesced per load
            int g = blockBase + e;
            if (g < 0) g = 0;                            // block 0, strip -1: unused
            q[b] = x[g];
        }
        #pragma unroll
        for (int b = 0; b < NB; ++b) {
            const int e = (i * NB + b) * BLOCK + tid;
            const float s0 = fmaf(M00,q[b].x, fmaf(M01,q[b].y, fmaf(M02,q[b].z, fmaf(M03,q[b].w, c0))));
            const float s1 = fmaf(M10,q[b].x, fmaf(M11,q[b].y, fmaf(M12,q[b].z, fmaf(M13,q[b].w, c1))));
            ss[e >> 6][e & 63] = make_float2(s0, s1);
        }
    }
    __syncthreads();                                      // 1 warp: cheap

    // ---- recurrence ----
    float y0_ = 0.f, y1_ = 0.f;
    auto step = [&](const float2 s) {
        const float n0 = fmaxf(fmaf(B00,y0_, fmaf(B01,y1_, s.x)), 0.f);
        const float n1 = fmaxf(fmaf(B10,y0_, fmaf(B11,y1_, s.y)), 0.f);
        y0_ = n0; y1_ = n1;
    };

    // warm: strip tid (= previous chunk). Block 0 / thread 0 starts exactly at y=0.
    if ((blockIdx.x | tid) != 0) {
        #pragma unroll 8
        for (int j = 0; j < WARM; ++j) step(ss[tid][j]);
    }

    // main: strip tid+1; head + swizzled staging, drain every 16 steps (128B runs)
    const int sm     = tid + 1;
    const int o4base = (int)blockIdx.x * 1024;   // block covers 1024 float4 of out

    #pragma unroll
    for (int seg = 0; seg < 4; ++seg) {
        #pragma unroll
        for (int p = 0; p < 8; ++p) {             // p = float4 (2-step pair) in segment
            step(ss[sm][seg*16 + 2*p]);
            const float z0 = fmaf(w00,y0_, fmaf(w01,y1_, v0));
            const float z1 = fmaf(w10,y0_, fmaf(w11,y1_, v1));
            const float r0 = rcp_approx(1.f + ex2_approx(z0));
            const float r1 = rcp_approx(1.f + ex2_approx(z1));

            step(ss[sm][seg*16 + 2*p + 1]);
            const float z2 = fmaf(w00,y0_, fmaf(w01,y1_, v0));
            const float z3 = fmaf(w10,y0_, fmaf(w11,y1_, v1));
            const float r2 = rcp_approx(1.f + ex2_approx(z2));
            const float r3 = rcp_approx(1.f + ex2_approx(z3));

            so[tid * 8 + ((tid ^ p) & 7)] = make_float4(r0, r1, r2, r3);
        }
        __syncwarp();

        #pragma unroll
        for (int l = 0; l < 8; ++l) {             // drain: 128B contiguous per strip
            const int e = l * BLOCK + tid;
            const int u = e >> 3;
            const int p = e & 7;
            out4[o4base + u * 32 + seg * 8 + p] = so[u * 8 + ((u ^ p) & 7)];
        }
        __syncwarp();
    }
}

extern "C" void kernel_launch(void* const* d_in, const int* in_sizes, int n_in,
                              void* d_out, int out_size)
{
    rdnnc_kernel<<<GRID, BLOCK>>>(
        (const float4*)d_in[0],
        (const float*)d_in[1], (const float*)d_in[2],
        (const float*)d_in[3], (const float*)d_in[4],
        (const float*)d_in[5], (const float*)d_in[6],
        (float4*)d_out);
}